// round 16
// baseline (speedup 1.0000x reference)
#include <cuda_runtime.h>
#include <cuda_bf16.h>
#include <math.h>
#include <stdint.h>

// Problem constants
#define BB    2
#define SS    2048
#define HID   2048
#define NH    32
#define NKV   8
#define DD    64
#define GQ    4                 // NH / NKV
#define MROWS (BB*SS)           // 4096
#define QGC   (2*NH*DD)         // 4096 columns of QG
#define KC    (NKV*DD)          // 512  columns of K proj
#define YC    (NH*DD)           // 2048 columns of attention output

// Scratch (device globals: allocation-free rule)
__device__ float g_QG[(size_t)MROWS * QGC];   // 4096 x 4096  (q | gate)
__device__ float g_K [(size_t)MROWS * KC];    // 4096 x 512
__device__ float g_Y [(size_t)MROWS * YC];    // attn out (pre-gate)

// bf16 hi/lo decompositions of GEMM operands (x = hi + lo, residual ~2^-18)
__device__ __nv_bfloat16 g_hhb[(size_t)MROWS * HID];
__device__ __nv_bfloat16 g_hlb[(size_t)MROWS * HID];
__device__ __nv_bfloat16 g_wqhb[(size_t)HID * QGC];
__device__ __nv_bfloat16 g_wqlb[(size_t)HID * QGC];
__device__ __nv_bfloat16 g_wkhb[(size_t)HID * KC];
__device__ __nv_bfloat16 g_wklb[(size_t)HID * KC];
__device__ __nv_bfloat16 g_wohb[(size_t)HID * HID];
__device__ __nv_bfloat16 g_wolb[(size_t)HID * HID];
__device__ __nv_bfloat16 g_Yhb[(size_t)MROWS * YC];
__device__ __nv_bfloat16 g_Ylb[(size_t)MROWS * YC];

// ---------------------------------------------------------------------------
// Helpers
// ---------------------------------------------------------------------------
__device__ __forceinline__ uint32_t smem_u32(const void* p) {
    return (uint32_t)__cvta_generic_to_shared(p);
}
__device__ __forceinline__ float tf32_rna(float x) {
    uint32_t y;
    asm("cvt.rna.tf32.f32 %0, %1;" : "=r"(y) : "f"(x));
    return __uint_as_float(y);
}
#define CP_ASYNC16(dst_u32, src_ptr) \
    asm volatile("cp.async.cg.shared.global [%0], [%1], 16;\n" :: "r"(dst_u32), "l"(src_ptr))
#define CP_COMMIT() asm volatile("cp.async.commit_group;\n")

// tf32 m16n8k8 (attention kernel)
__device__ __forceinline__ void mma_tf32(float d[4],
                                         const uint32_t a[4],
                                         const uint32_t b[2]) {
    asm volatile(
        "mma.sync.aligned.m16n8k8.row.col.f32.tf32.tf32.f32 "
        "{%0,%1,%2,%3},{%4,%5,%6,%7},{%8,%9},{%0,%1,%2,%3};"
        : "+f"(d[0]), "+f"(d[1]), "+f"(d[2]), "+f"(d[3])
        : "r"(a[0]), "r"(a[1]), "r"(a[2]), "r"(a[3]),
          "r"(b[0]), "r"(b[1]));
}
// bf16 m16n8k16 (projection GEMMs)
__device__ __forceinline__ void mma_bf16(float d[4],
                                         const uint32_t a[4],
                                         const uint32_t b[2]) {
    asm volatile(
        "mma.sync.aligned.m16n8k16.row.col.f32.bf16.bf16.f32 "
        "{%0,%1,%2,%3},{%4,%5,%6,%7},{%8,%9},{%0,%1,%2,%3};"
        : "+f"(d[0]), "+f"(d[1]), "+f"(d[2]), "+f"(d[3])
        : "r"(a[0]), "r"(a[1]), "r"(a[2]), "r"(a[3]),
          "r"(b[0]), "r"(b[1]));
}
// ldmatrix: A fragments (row-major 16x16 bf16 -> mma A layout)
__device__ __forceinline__ void ldsm_x4(uint32_t r[4], uint32_t addr) {
    asm volatile(
        "ldmatrix.sync.aligned.m8n8.x4.shared.b16 {%0,%1,%2,%3}, [%4];"
        : "=r"(r[0]), "=r"(r[1]), "=r"(r[2]), "=r"(r[3]) : "r"(addr));
}
// ldmatrix.trans: B fragments ([k][n]-stored 16x16 bf16 -> mma col.b layout)
__device__ __forceinline__ void ldsm_x4_t(uint32_t r[4], uint32_t addr) {
    asm volatile(
        "ldmatrix.sync.aligned.m8n8.x4.trans.shared.b16 {%0,%1,%2,%3}, [%4];"
        : "=r"(r[0]), "=r"(r[1]), "=r"(r[2]), "=r"(r[3]) : "r"(addr));
}

// ---------------------------------------------------------------------------
// Split to bf16 hi/lo: hi = bf16(x), lo = bf16(x - hi). float4-vectorized.
// ---------------------------------------------------------------------------
__global__ void split_bf16_kernel(const float* __restrict__ x,
                                  __nv_bfloat16* __restrict__ hi,
                                  __nv_bfloat16* __restrict__ lo, int n4)
{
    int i = blockIdx.x * blockDim.x + threadIdx.x;
    if (i >= n4) return;
    float4 v = ((const float4*)x)[i];
    __nv_bfloat16 hx = __float2bfloat16_rn(v.x);
    __nv_bfloat16 hy = __float2bfloat16_rn(v.y);
    __nv_bfloat16 hz = __float2bfloat16_rn(v.z);
    __nv_bfloat16 hw = __float2bfloat16_rn(v.w);
    __nv_bfloat162* hp = (__nv_bfloat162*)hi;
    __nv_bfloat162* lp = (__nv_bfloat162*)lo;
    hp[2 * i]     = __nv_bfloat162(hx, hy);
    hp[2 * i + 1] = __nv_bfloat162(hz, hw);
    lp[2 * i]     = __nv_bfloat162(
        __float2bfloat16_rn(v.x - __bfloat162float(hx)),
        __float2bfloat16_rn(v.y - __bfloat162float(hy)));
    lp[2 * i + 1] = __nv_bfloat162(
        __float2bfloat16_rn(v.z - __bfloat162float(hz)),
        __float2bfloat16_rn(v.w - __bfloat162float(hw)));
}

// ---------------------------------------------------------------------------
// bf16x3 tensor-core GEMM: C = Ah*Bh + Ah*Bl + Al*Bh (residual ~2^-18).
// CTA tile 256x128x32, 256 threads, warp tile 64x64 (4m x 2n), m16n8k16,
// ldmatrix fragments, 3-stage cp.async pipeline, dynamic smem (~175KB).
// Warp tile 64x64 raises MAC-per-smem-byte 16 -> 24.5 vs 64x32.
// M%256==0, N%128==0, K%32==0.
// ---------------------------------------------------------------------------
#define TBM 256
#define TBN 128
#define TBK 32
#define NSTG 3
#define ATS 40    // A smem row stride (bf16): 80B -> r*5 mod 8 distinct (LDSM)
#define BTS 136   // B smem row stride (bf16): 272B -> r*17 mod 8 distinct (LDSM)
#define A_STG (TBM * ATS)   // 10240 bf16 per stage per matrix
#define B_STG (TBK * BTS)   // 4352 bf16 per stage per matrix
#define GEMM_SMEM ((2 * NSTG * A_STG + 2 * NSTG * B_STG) * 2)  // 175104 B

__global__ __launch_bounds__(256) void gemm_bf16x3(
    const __nv_bfloat16* __restrict__ Ah, const __nv_bfloat16* __restrict__ Al,
    const __nv_bfloat16* __restrict__ Bh, const __nv_bfloat16* __restrict__ Bl,
    float* __restrict__ C, int M, int ldn, int K)
{
    extern __shared__ __align__(16) __nv_bfloat16 dsm[];
    __nv_bfloat16* Ahs = dsm;                          // [NSTG][TBM][ATS]
    __nv_bfloat16* Als = Ahs + NSTG * A_STG;
    __nv_bfloat16* Bhs = Als + NSTG * A_STG;           // [NSTG][TBK][BTS]
    __nv_bfloat16* Bls = Bhs + NSTG * B_STG;

    const int t    = threadIdx.x;
    const int warp = t >> 5;
    const int lane = t & 31;
    const int row0 = blockIdx.y * TBM;
    const int col0 = blockIdx.x * TBN;

    const int wm = (warp >> 1) * 64;   // 4 (m) x 2 (n) warps
    const int wn = (warp & 1) * 64;

    // ldmatrix lane->address mapping
    const int lrow = lane & 15;        // row within 16-row block
    const int lsel = (lane >> 4) * 8;  // 0 or 8: which 16B column chunk

    float acc[4][8][4] = {};           // [mt][nt][reg]
    const int NT = K / TBK;

    // cp.async mapping: A 256x32 = 1024 chunks of 8 bf16 (4/thread);
    //                   B  32x128 = 512 chunks (2/thread)
    auto load_tile = [&](int it, int stg) {
        const int k0 = it * TBK;
        __nv_bfloat16* As_h = Ahs + stg * A_STG;
        __nv_bfloat16* As_l = Als + stg * A_STG;
        __nv_bfloat16* Bs_h = Bhs + stg * B_STG;
        __nv_bfloat16* Bs_l = Bls + stg * B_STG;
        #pragma unroll
        for (int i = 0; i < 4; ++i) {
            int c  = t + i * 256;          // 0..1023
            int r  = c >> 2;               // 0..255
            int kc = (c & 3) * 8;          // 0,8,16,24
            size_t off = (size_t)(row0 + r) * K + k0 + kc;
            CP_ASYNC16(smem_u32(As_h + r * ATS + kc), Ah + off);
            CP_ASYNC16(smem_u32(As_l + r * ATS + kc), Al + off);
        }
        #pragma unroll
        for (int i = 0; i < 2; ++i) {
            int c  = t + i * 256;          // 0..511
            int kr = c >> 4;               // 0..31
            int nc = (c & 15) * 8;         // 0..120
            size_t off = (size_t)(k0 + kr) * ldn + col0 + nc;
            CP_ASYNC16(smem_u32(Bs_h + kr * BTS + nc), Bh + off);
            CP_ASYNC16(smem_u32(Bs_l + kr * BTS + nc), Bl + off);
        }
        CP_COMMIT();
    };

    load_tile(0, 0);
    if (NT > 1) load_tile(1, 1);

    for (int it = 0; it < NT; ++it) {
        if (it + 2 < NT) load_tile(it + 2, (it + 2) % NSTG);

        int allow = NT - 1 - it; if (allow > 2) allow = 2;
        if (allow == 2)      asm volatile("cp.async.wait_group 2;\n");
        else if (allow == 1) asm volatile("cp.async.wait_group 1;\n");
        else                 asm volatile("cp.async.wait_group 0;\n");
        __syncthreads();

        const int stg = it % NSTG;
        const __nv_bfloat16* As_h = Ahs + stg * A_STG;
        const __nv_bfloat16* As_l = Als + stg * A_STG;
        const __nv_bfloat16* Bs_h = Bhs + stg * B_STG;
        const __nv_bfloat16* Bs_l = Bls + stg * B_STG;

        #pragma unroll
        for (int ks = 0; ks < 2; ++ks) {
            const int kb = ks * 16;
            uint32_t ah[4][4], al[4][4];
            #pragma unroll
            for (int mt = 0; mt < 4; ++mt) {
                const int m = wm + mt * 16 + lrow;
                ldsm_x4(ah[mt], smem_u32(As_h + m * ATS + kb + lsel));
                ldsm_x4(al[mt], smem_u32(As_l + m * ATS + kb + lsel));
            }
            // B per 16-col group, loaded inside the loop to bound live regs
            #pragma unroll
            for (int g = 0; g < 4; ++g) {
                const int n = wn + g * 16 + lsel;
                uint32_t bh[4], bl[4];
                ldsm_x4_t(bh, smem_u32(Bs_h + (kb + lrow) * BTS + n));
                ldsm_x4_t(bl, smem_u32(Bs_l + (kb + lrow) * BTS + n));
                #pragma unroll
                for (int mt = 0; mt < 4; ++mt)
                    #pragma unroll
                    for (int half = 0; half < 2; ++half) {
                        const int nt = g * 2 + half;
                        mma_bf16(acc[mt][nt], ah[mt], &bh[half * 2]);
                        mma_bf16(acc[mt][nt], ah[mt], &bl[half * 2]);
                        mma_bf16(acc[mt][nt], al[mt], &bh[half * 2]);
                    }
            }
        }
        __syncthreads();
    }

    #pragma unroll
    for (int mt = 0; mt < 4; ++mt) {
        #pragma unroll
        for (int nt = 0; nt < 8; ++nt) {
            int r = row0 + wm + mt * 16 + (lane >> 2);
            int c = col0 + wn + nt * 8 + (lane & 3) * 2;
            float2* p0 = (float2*)(C + (size_t)r * ldn + c);
            float2* p1 = (float2*)(C + (size_t)(r + 8) * ldn + c);
            *p0 = make_float2(acc[mt][nt][0], acc[mt][nt][1]);
            *p1 = make_float2(acc[mt][nt][2], acc[mt][nt][3]);
        }
    }
}

// ---------------------------------------------------------------------------
// RoPE in place (unchanged).
// ---------------------------------------------------------------------------
__global__ void rope_kernel(float* __restrict__ x,
                            const float* __restrict__ cs,
                            const float* __restrict__ sn,
                            int nheads, int stride)
{
    int idx = blockIdx.x * blockDim.x + threadIdx.x;
    int total = MROWS * nheads * (DD / 2);
    if (idx >= total) return;
    int d   = idx & 31;
    int h   = (idx >> 5) % nheads;
    int row = idx / (nheads * 32);
    int s   = row & (SS - 1);

    float* p = x + (size_t)row * stride + h * DD;
    float v1 = p[d];
    float v2 = p[d + 32];
    float c  = cs[s * DD + d];
    float sv = sn[s * DD + d];
    p[d]      = v1 * c - v2 * sv;
    p[d + 32] = v2 * c + v1 * sv;
}

// ---------------------------------------------------------------------------
// Tensor-core flash attention (unchanged from round 10).
// S = Q K^T at 3xTF32; O = P K at 1xTF32. K used as V (faithful).
// ---------------------------------------------------------------------------
#define FAS 68
#define FA_SMEM ((5 * 64 * FAS + 256) * 4)

__global__ __launch_bounds__(256) void flash_attn_tc(
    const float* __restrict__ Q,
    const float* __restrict__ Kc,
    float* __restrict__ Y)
{
    extern __shared__ __align__(16) float fsm[];
    float (*Qh)[FAS] = (float (*)[FAS])(fsm);
    float (*Ql)[FAS] = (float (*)[FAS])(fsm + 64 * FAS);
    float (*Kh)[FAS] = (float (*)[FAS])(fsm + 2 * 64 * FAS);
    float (*Kl)[FAS] = (float (*)[FAS])(fsm + 3 * 64 * FAS);
    float (*Ps)[FAS] = (float (*)[FAS])(fsm + 4 * 64 * FAS);
    float* redm = fsm + 5 * 64 * FAS;
    float* reds = redm + 128;

    const int qt = blockIdx.x, h = blockIdx.y, b = blockIdx.z;
    const int kh = h / GQ;
    const int t = threadIdx.x, w = t >> 5, lane = t & 31;
    const int fm = lane >> 2, fk = lane & 3;
    const int wm = (w >> 1) * 16;
    const int wn = (w & 1) * 32;
    const int q0 = qt * 64;

    const float* Qbase = Q + (size_t)(b * SS + q0) * QGC + h * DD;
    #pragma unroll
    for (int i = 0; i < 4; ++i) {
        int e = t + i * 256;
        int r = e >> 4, d4 = (e & 15) * 4;
        float4 v = *(const float4*)(Qbase + (size_t)r * QGC + d4);
        float4 hi, lo;
        hi.x = tf32_rna(v.x); lo.x = v.x - hi.x;
        hi.y = tf32_rna(v.y); lo.y = v.y - hi.y;
        hi.z = tf32_rna(v.z); lo.z = v.z - hi.z;
        hi.w = tf32_rna(v.w); lo.w = v.w - hi.w;
        *(float4*)&Qh[r][d4] = hi;
        *(float4*)&Ql[r][d4] = lo;
    }

    float m_i[2] = {-INFINITY, -INFINITY};
    float l_i[2] = {0.f, 0.f};
    float o[4][4] = {};

    for (int kt = 0; kt <= qt; ++kt) {
        __syncthreads();
        const float* Kbase = Kc + (size_t)(b * SS + kt * 64) * KC + kh * DD;
        #pragma unroll
        for (int i = 0; i < 4; ++i) {
            int e = t + i * 256;
            int r = e >> 4, d4 = (e & 15) * 4;
            float4 v = *(const float4*)(Kbase + (size_t)r * KC + d4);
            float4 hi, lo;
            hi.x = tf32_rna(v.x); lo.x = v.x - hi.x;
            hi.y = tf32_rna(v.y); lo.y = v.y - hi.y;
            hi.z = tf32_rna(v.z); lo.z = v.z - hi.z;
            hi.w = tf32_rna(v.w); lo.w = v.w - hi.w;
            *(float4*)&Kh[r][d4] = hi;
            *(float4*)&Kl[r][d4] = lo;
        }
        __syncthreads();

        float s[4][4] = {};
        #pragma unroll
        for (int kb = 0; kb < 64; kb += 8) {
            uint32_t ah[4], al[4];
            ah[0] = __float_as_uint(Qh[wm + fm    ][kb + fk    ]);
            ah[1] = __float_as_uint(Qh[wm + fm + 8][kb + fk    ]);
            ah[2] = __float_as_uint(Qh[wm + fm    ][kb + fk + 4]);
            ah[3] = __float_as_uint(Qh[wm + fm + 8][kb + fk + 4]);
            al[0] = __float_as_uint(Ql[wm + fm    ][kb + fk    ]);
            al[1] = __float_as_uint(Ql[wm + fm + 8][kb + fk    ]);
            al[2] = __float_as_uint(Ql[wm + fm    ][kb + fk + 4]);
            al[3] = __float_as_uint(Ql[wm + fm + 8][kb + fk + 4]);
            #pragma unroll
            for (int nt = 0; nt < 4; ++nt) {
                const int n = wn + nt * 8;
                uint32_t bh[2], bl[2];
                bh[0] = __float_as_uint(Kh[n + fm][kb + fk    ]);
                bh[1] = __float_as_uint(Kh[n + fm][kb + fk + 4]);
                bl[0] = __float_as_uint(Kl[n + fm][kb + fk    ]);
                bl[1] = __float_as_uint(Kl[n + fm][kb + fk + 4]);
                mma_tf32(s[nt], ah, bh);
                mma_tf32(s[nt], ah, bl);
                mma_tf32(s[nt], al, bh);
            }
        }

        if (kt == qt) {
            #pragma unroll
            for (int nt = 0; nt < 4; ++nt)
                #pragma unroll
                for (int j = 0; j < 4; ++j) {
                    int rl = wm + fm + ((j >> 1) << 3);
                    int cl = wn + nt * 8 + 2 * fk + (j & 1);
                    if (cl > rl) s[nt][j] = -INFINITY;
                }
        }

        float mx[2] = {-INFINITY, -INFINITY};
        #pragma unroll
        for (int nt = 0; nt < 4; ++nt) {
            mx[0] = fmaxf(mx[0], fmaxf(s[nt][0], s[nt][1]));
            mx[1] = fmaxf(mx[1], fmaxf(s[nt][2], s[nt][3]));
        }
        #pragma unroll
        for (int r = 0; r < 2; ++r) {
            mx[r] = fmaxf(mx[r], __shfl_xor_sync(0xffffffffu, mx[r], 1));
            mx[r] = fmaxf(mx[r], __shfl_xor_sync(0xffffffffu, mx[r], 2));
        }
        if (fk == 0) {
            redm[(w & 1) * 64 + wm + fm    ] = mx[0];
            redm[(w & 1) * 64 + wm + fm + 8] = mx[1];
        }
        __syncthreads();

        float m_new[2], scl[2];
        #pragma unroll
        for (int r = 0; r < 2; ++r) {
            int row = wm + fm + r * 8;
            float mt2 = fmaxf(redm[row], redm[64 + row]);
            m_new[r] = fmaxf(m_i[r], mt2);
            scl[r] = __expf(m_i[r] - m_new[r]);
        }

        float rs[2] = {0.f, 0.f};
        #pragma unroll
        for (int nt = 0; nt < 4; ++nt)
            #pragma unroll
            for (int j = 0; j < 4; ++j) {
                int r = j >> 1;
                float p = __expf(s[nt][j] - m_new[r]);
                rs[r] += p;
                Ps[wm + fm + (r << 3)][wn + nt * 8 + 2 * fk + (j & 1)] = tf32_rna(p);
            }
        #pragma unroll
        for (int r = 0; r < 2; ++r) {
            rs[r] += __shfl_xor_sync(0xffffffffu, rs[r], 1);
            rs[r] += __shfl_xor_sync(0xffffffffu, rs[r], 2);
        }
        if (fk == 0) {
            reds[(w & 1) * 64 + wm + fm    ] = rs[0];
            reds[(w & 1) * 64 + wm + fm + 8] = rs[1];
        }
        __syncthreads();

        #pragma unroll
        for (int r = 0; r < 2; ++r) {
            int row = wm + fm + r * 8;
            l_i[r] = l_i[r] * scl[r] + reds[row] + reds[64 + row];
            m_i[r] = m_new[r];
        }
        #pragma unroll
        for (int nt = 0; nt < 4; ++nt)
            #pragma unroll
            for (int j = 0; j < 4; ++j)
                o[nt][j] *= scl[j >> 1];

        #pragma unroll
        for (int kb = 0; kb < 64; kb += 8) {
            uint32_t ap[4];
            ap[0] = __float_as_uint(Ps[wm + fm    ][kb + fk    ]);
            ap[1] = __float_as_uint(Ps[wm + fm + 8][kb + fk    ]);
            ap[2] = __float_as_uint(Ps[wm + fm    ][kb + fk + 4]);
            ap[3] = __float_as_uint(Ps[wm + fm + 8][kb + fk + 4]);
            #pragma unroll
            for (int nt = 0; nt < 4; ++nt) {
                const int n = wn + nt * 8;
                uint32_t bo[2];
                bo[0] = __float_as_uint(Kh[kb + fk    ][n + fm]);
                bo[1] = __float_as_uint(Kh[kb + fk + 4][n + fm]);
                mma_tf32(o[nt], ap, bo);
            }
        }
    }

    #pragma unroll
    for (int r = 0; r < 2; ++r) {
        float inv = 1.f / l_i[r];
        int row = q0 + wm + fm + r * 8;
        float* yp = Y + (size_t)(b * SS + row) * YC + h * DD;
        #pragma unroll
        for (int nt = 0; nt < 4; ++nt) {
            int col = wn + nt * 8 + 2 * fk;
            *(float2*)(yp + col) =
                make_float2(o[nt][2 * r] * inv, o[nt][2 * r + 1] * inv);
        }
    }
}

// ---------------------------------------------------------------------------
// Gate + bf16 split: w = Y * sigmoid(gate); (Yh, Yl) = bf16 hi/lo of w.
// ---------------------------------------------------------------------------
__global__ void gate_split_bf16_kernel(const float* __restrict__ y,
                                       const float* __restrict__ qg,
                                       __nv_bfloat16* __restrict__ yh,
                                       __nv_bfloat16* __restrict__ yl)
{
    int idx = blockIdx.x * blockDim.x + threadIdx.x;
    int total4 = MROWS * YC / 4;
    if (idx >= total4) return;
    int row  = idx / (YC / 4);
    int col4 = (idx % (YC / 4)) * 4;
    float4 g = *(const float4*)(qg + (size_t)row * QGC + YC + col4);
    float4 v = *(const float4*)(y + (size_t)row * YC + col4);
    v.x *= 1.f / (1.f + __expf(-g.x));
    v.y *= 1.f / (1.f + __expf(-g.y));
    v.z *= 1.f / (1.f + __expf(-g.z));
    v.w *= 1.f / (1.f + __expf(-g.w));
    __nv_bfloat16 hx = __float2bfloat16_rn(v.x);
    __nv_bfloat16 hy = __float2bfloat16_rn(v.y);
    __nv_bfloat16 hz = __float2bfloat16_rn(v.z);
    __nv_bfloat16 hw = __float2bfloat16_rn(v.w);
    size_t o2 = (size_t)row * (YC / 2) + (idx % (YC / 4)) * 2;
    ((__nv_bfloat162*)yh)[o2]     = __nv_bfloat162(hx, hy);
    ((__nv_bfloat162*)yh)[o2 + 1] = __nv_bfloat162(hz, hw);
    ((__nv_bfloat162*)yl)[o2]     = __nv_bfloat162(
        __float2bfloat16_rn(v.x - __bfloat162float(hx)),
        __float2bfloat16_rn(v.y - __bfloat162float(hy)));
    ((__nv_bfloat162*)yl)[o2 + 1] = __nv_bfloat162(
        __float2bfloat16_rn(v.z - __bfloat162float(hz)),
        __float2bfloat16_rn(v.w - __bfloat162float(hw)));
}

// ---------------------------------------------------------------------------
// Launch: inputs per metadata order:
// 0 hidden_states, 1 cos, 2 sin, 3 attention_mask (unused; known causal),
// 4 wq, 5 wk, 6 wv (unused: v never affects output), 7 wo
// ---------------------------------------------------------------------------
extern "C" void kernel_launch(void* const* d_in, const int* in_sizes, int n_in,
                              void* d_out, int out_size)
{
    const float* hidden = (const float*)d_in[0];
    const float* cosp   = (const float*)d_in[1];
    const float* sinp   = (const float*)d_in[2];
    const float* wq     = (const float*)d_in[4];
    const float* wk     = (const float*)d_in[5];
    const float* wo     = (const float*)d_in[7];
    float* out = (float*)d_out;

    float *QG, *Kp, *Y;
    __nv_bfloat16 *hh, *hl, *wqh, *wql, *wkh, *wkl, *woh, *wol, *Yh, *Yl;
    cudaGetSymbolAddress((void**)&QG, g_QG);
    cudaGetSymbolAddress((void**)&Kp, g_K);
    cudaGetSymbolAddress((void**)&Y,  g_Y);
    cudaGetSymbolAddress((void**)&hh, g_hhb);
    cudaGetSymbolAddress((void**)&hl, g_hlb);
    cudaGetSymbolAddress((void**)&wqh, g_wqhb);
    cudaGetSymbolAddress((void**)&wql, g_wqlb);
    cudaGetSymbolAddress((void**)&wkh, g_wkhb);
    cudaGetSymbolAddress((void**)&wkl, g_wklb);
    cudaGetSymbolAddress((void**)&woh, g_wohb);
    cudaGetSymbolAddress((void**)&wol, g_wolb);
    cudaGetSymbolAddress((void**)&Yh, g_Yhb);
    cudaGetSymbolAddress((void**)&Yl, g_Ylb);

    cudaFuncSetAttribute(gemm_bf16x3,
                         cudaFuncAttributeMaxDynamicSharedMemorySize, GEMM_SMEM);
    cudaFuncSetAttribute(flash_attn_tc,
                         cudaFuncAttributeMaxDynamicSharedMemorySize, FA_SMEM);

    // 0) bf16 hi/lo splits of GEMM operands
    {
        int n4;
        n4 = MROWS * HID / 4; split_bf16_kernel<<<(n4 + 255) / 256, 256>>>(hidden, hh, hl, n4);
        n4 = HID * QGC / 4;   split_bf16_kernel<<<(n4 + 255) / 256, 256>>>(wq, wqh, wql, n4);
        n4 = HID * KC / 4;    split_bf16_kernel<<<(n4 + 255) / 256, 256>>>(wk, wkh, wkl, n4);
        n4 = HID * HID / 4;   split_bf16_kernel<<<(n4 + 255) / 256, 256>>>(wo, woh, wol, n4);
    }
    // 1) QG = hidden @ wq   [4096 x 4096]
    gemm_bf16x3<<<dim3(QGC / TBN, MROWS / TBM), 256, GEMM_SMEM>>>(
        hh, hl, wqh, wql, QG, MROWS, QGC, HID);
    // 2) K = hidden @ wk    [4096 x 512]
    gemm_bf16x3<<<dim3(KC / TBN, MROWS / TBM), 256, GEMM_SMEM>>>(
        hh, hl, wkh, wkl, Kp, MROWS, KC, HID);
    // 3) RoPE on Q half of QG and on K
    {
        int tq = MROWS * NH * (DD / 2);
        rope_kernel<<<(tq + 255) / 256, 256>>>(QG, cosp, sinp, NH, QGC);
        int tk = MROWS * NKV * (DD / 2);
        rope_kernel<<<(tk + 255) / 256, 256>>>(Kp, cosp, sinp, NKV, KC);
    }
    // 4) Tensor-core flash attention (K doubles as V, faithful to reference)
    flash_attn_tc<<<dim3(SS / 64, NH, BB), 256, FA_SMEM>>>(QG, Kp, Y);
    // 5) Gate + bf16 split of gated Y
    {
        int total4 = MROWS * YC / 4;
        gate_split_bf16_kernel<<<(total4 + 255) / 256, 256>>>(Y, QG, Yh, Yl);
    }
    // 6) out = Y @ wo  [4096 x 2048]  (bf16x3)
    gemm_bf16x3<<<dim3(HID / TBN, MROWS / TBM), 256, GEMM_SMEM>>>(
        Yh, Yl, woh, wol, out, MROWS, HID, HID);
}